// round 13
// baseline (speedup 1.0000x reference)
#include <cuda_runtime.h>
#include <math.h>

#define RULES 512
#define FEAT  128
#define RES   5
#define BATCH 2048
#define WARPS_PER_BLOCK 16
#define THREADS (WARPS_PER_BLOCK * 32)          // 512 == RULES
#define BLOCKS  (BATCH / WARPS_PER_BLOCK)       // 128  (single wave, 1 block/SM)
#define PAIRS 8                                 // 16 rules/lane as 8 (A,B) pairs

#define LOG2E 1.4426950408889634f

__device__ __forceinline__ float ex2f(float v) {
    float r;
    asm("ex2.approx.f32 %0, %1;" : "=f"(r) : "f"(v));
    return r;
}
__device__ __forceinline__ float rcpf(float v) {
    float r;
    asm("rcp.approx.f32 %0, %1;" : "=f"(r) : "f"(v));
    return r;
}

__global__ void __launch_bounds__(THREADS, 1)
fused_kernel(const float* __restrict__ x,
             const float* __restrict__ a,
             const float* __restrict__ bmat,
             const float* __restrict__ r,
             const float* __restrict__ d,
             float* __restrict__ out) {
    // Rule-PAIR packed constants. Pair p = m*32+l covers rules A=m*64+l, B=A+32.
    // sK4[p] = (k0A, k1A, k0B, k1B) log2-domain, 1/5 x-scale folded into k1,
    // row-common term dropped (cancels in ratio).
    __shared__ float4 sK4[RULES / 2];
    __shared__ float4 sB[RULES];          // beliefs 0..3 per rule
    __shared__ float2 sB42[RULES / 2];    // (b4 of A, b4 of B) per pair

    const int t = threadIdx.x;
    const int l = t & 31;
    const int w = t >> 5;
    const int row = blockIdx.x * WARPS_PER_BLOCK + w;

    // Issue ALL global loads first; latency overlaps Sx tree + prep math.
    const float4 xv = *reinterpret_cast<const float4*>(x + row * FEAT + l * 4);
    const float av = a[t];
    const float rv = r[t];
    float bv[RES];
    #pragma unroll
    for (int j = 0; j < RES; j++) bv[j] = bmat[t * RES + j];
    const float ed = __expf(d[0]);

    // ---- Sx over raw features (scale folded into K1); hides prep LDG latency
    float Sx = (xv.x + xv.y) + (xv.z + xv.w);
    #pragma unroll
    for (int o = 16; o; o >>= 1) Sx += __shfl_xor_sync(0xffffffffu, Sx, o);

    // ---- prep: thread t preps rule t; writes into pair-packed layout ----
    {
        const int m     = t >> 6;          // pair group 0..7
        const int which = (t >> 5) & 1;    // A(0) or B(1) within pair
        const int p     = m * 32 + l;      // pair index

        float k1 = 0.4f * ed * av;                  // 2*e^d*a * (1/5)
        float k0 = rv - ed * 128.0f * av * av;
        float* kf = reinterpret_cast<float*>(sK4);
        kf[p * 4 + which * 2 + 0] = k0 * LOG2E;
        kf[p * 4 + which * 2 + 1] = k1 * LOG2E;

        // softmax without max-subtraction: |b| ~ N(0,1), no overflow risk,
        // and softmax is shift-invariant (deletes 9 ops from pre-barrier path)
        float sum = 0.f;
        #pragma unroll
        for (int j = 0; j < RES; j++) { bv[j] = ex2f(bv[j] * LOG2E); sum += bv[j]; }
        float inv = rcpf(sum);
        sB[t] = make_float4(bv[0] * inv, bv[1] * inv, bv[2] * inv, bv[3] * inv);
        reinterpret_cast<float*>(sB42)[p * 2 + which] = bv[4] * inv;
    }
    __syncthreads();                       // the ONLY block barrier

    // ---- rule activations: 8 pairs, 2 independent accumulation chains ----
    float awA[PAIRS], awB[PAIRS];
    float sp0 = 0.f, sp1 = 0.f;
    #pragma unroll
    for (int m = 0; m < PAIRS; m++) {
        float4 K = sK4[m * 32 + l];
        float a0 = ex2f(fmaf(K.y, Sx, K.x));
        float a1 = ex2f(fmaf(K.w, Sx, K.z));
        awA[m] = a0; awB[m] = a1;
        sp0 += a0; sp1 += a1;
    }
    float spart = sp0 + sp1;
    #pragma unroll
    for (int o = 16; o; o >>= 1) spart += __shfl_xor_sync(0xffffffffu, spart, o);
    const float s = spart;

    // ---- evidential combine: 10 independent product chains (A/B split) ----
    float pA0 = 1.f, pA1 = 1.f, pA2 = 1.f, pA3 = 1.f, pA4 = 1.f;
    float pB0 = 1.f, pB1 = 1.f, pB2 = 1.f, pB3 = 1.f, pB4 = 1.f;
    #pragma unroll
    for (int m = 0; m < PAIRS; m++) {
        int rA = m * 64 + l;
        float ratioA = awA[m] * rcpf(s - awA[m]);
        float ratioB = awB[m] * rcpf(s - awB[m]);
        float4 bA = sB[rA];
        float4 bB = sB[rA + 32];
        float2 b4 = sB42[m * 32 + l];
        pA0 *= fmaf(ratioA, bA.x, 1.0f);
        pA1 *= fmaf(ratioA, bA.y, 1.0f);
        pA2 *= fmaf(ratioA, bA.z, 1.0f);
        pA3 *= fmaf(ratioA, bA.w, 1.0f);
        pA4 *= fmaf(ratioA, b4.x, 1.0f);
        pB0 *= fmaf(ratioB, bB.x, 1.0f);
        pB1 *= fmaf(ratioB, bB.y, 1.0f);
        pB2 *= fmaf(ratioB, bB.z, 1.0f);
        pB3 *= fmaf(ratioB, bB.w, 1.0f);
        pB4 *= fmaf(ratioB, b4.y, 1.0f);
    }
    float p0 = pA0 * pB0, p1 = pA1 * pB1, p2 = pA2 * pB2,
          p3 = pA3 * pB3, p4 = pA4 * pB4;
    // 5 independent cross-lane product reductions (pipelined SHFL chains)
    #pragma unroll
    for (int o = 16; o; o >>= 1) {
        p0 *= __shfl_xor_sync(0xffffffffu, p0, o);
        p1 *= __shfl_xor_sync(0xffffffffu, p1, o);
        p2 *= __shfl_xor_sync(0xffffffffu, p2, o);
        p3 *= __shfl_xor_sync(0xffffffffu, p3, o);
        p4 *= __shfl_xor_sync(0xffffffffu, p4, o);
    }

    if (l == 0) {
        float b0 = p0 - 1.f, b1 = p1 - 1.f, b2 = p2 - 1.f, b3 = p3 - 1.f, b4 = p4 - 1.f;
        float bsum = b0 + b1 + b2 + b3 + b4;
        float acc = fmaf(b0, -0.5f, 0.f);
        acc = fmaf(b2, 0.5f, acc);
        acc = fmaf(b3, 1.0f, acc);
        acc = fmaf(b4, 1.5f, acc);
        out[row] = acc * rcpf(bsum);
    }
}

extern "C" void kernel_launch(void* const* d_in, const int* in_sizes, int n_in,
                              void* d_out, int out_size) {
    const float* x = (const float*)d_in[0];
    const float* a = (const float*)d_in[1];
    const float* b = (const float*)d_in[2];
    const float* r = (const float*)d_in[3];
    const float* d = (const float*)d_in[4];
    float* out = (float*)d_out;

    fused_kernel<<<BLOCKS, THREADS>>>(x, a, b, r, d, out);
}

// round 14
// speedup vs baseline: 2.2324x; 2.2324x over previous
#include <cuda_runtime.h>
#include <math.h>

#define RULES 512
#define FEAT  128
#define RES   5
#define BATCH 2048
#define WARPS_PER_BLOCK 16
#define THREADS (WARPS_PER_BLOCK * 32)          // 512 == RULES
#define BLOCKS  (BATCH / WARPS_PER_BLOCK)       // 128  (single wave, 1 block/SM)
#define PAIRS 8                                 // 16 rules/lane as 8 (A,B) pairs

#define LOG2E 1.4426950408889634f

__device__ __forceinline__ float ex2f(float v) {
    float r;
    asm("ex2.approx.f32 %0, %1;" : "=f"(r) : "f"(v));
    return r;
}
__device__ __forceinline__ float rcpf(float v) {
    float r;
    asm("rcp.approx.f32 %0, %1;" : "=f"(r) : "f"(v));
    return r;
}

__global__ void __launch_bounds__(THREADS, 1)
fused_kernel(const float* __restrict__ x,
             const float* __restrict__ a,
             const float* __restrict__ bmat,
             const float* __restrict__ r,
             const float* __restrict__ d,
             float* __restrict__ out) {
    // Rule-PAIR packed constants. Pair p = m*32+l covers rules A=m*64+l, B=A+32.
    // sK4[p] = (k0A, k1A, k0B, k1B) in log2 domain, 1/5 x-scale folded into k1,
    // row-common quadratic term dropped (cancels in ratio = aw/(s-aw)).
    __shared__ float4 sK4[RULES / 2];     // 8 LDS.128 per lane instead of 16 LDS.64
    __shared__ float4 sB[RULES];          // beliefs 0..3 per rule
    __shared__ float2 sB42[RULES / 2];    // (b4 of A, b4 of B) per pair

    const int t = threadIdx.x;
    const int l = t & 31;
    const int w = t >> 5;
    const int row = blockIdx.x * WARPS_PER_BLOCK + w;

    // Issue ALL global loads first; latency overlaps Sx tree + prep math.
    const float4 xv = *reinterpret_cast<const float4*>(x + row * FEAT + l * 4);
    const float av = a[t];
    const float rv = r[t];
    float bv[RES];
    #pragma unroll
    for (int j = 0; j < RES; j++) bv[j] = bmat[t * RES + j];
    const float ed = __expf(d[0]);

    // ---- Sx over raw features (scale folded into K1); hides prep LDG latency
    float Sx = (xv.x + xv.y) + (xv.z + xv.w);
    #pragma unroll
    for (int o = 16; o; o >>= 1) Sx += __shfl_xor_sync(0xffffffffu, Sx, o);

    // ---- prep: thread t preps rule t; writes into pair-packed layout ----
    {
        const int m     = t >> 6;          // pair group 0..7
        const int which = (t >> 5) & 1;    // A(0) or B(1) within pair
        const int p     = m * 32 + l;      // pair index

        float k1 = 0.4f * ed * av;                  // 2*e^d*a * (1/5)
        float k0 = rv - ed * 128.0f * av * av;      // common-mode C term dropped
        float* kf = reinterpret_cast<float*>(sK4);
        kf[p * 4 + which * 2 + 0] = k0 * LOG2E;
        kf[p * 4 + which * 2 + 1] = k1 * LOG2E;

        float mx = fmaxf(fmaxf(fmaxf(bv[0], bv[1]), fmaxf(bv[2], bv[3])), bv[4]);
        float sum = 0.f;
        #pragma unroll
        for (int j = 0; j < RES; j++) { bv[j] = ex2f((bv[j] - mx) * LOG2E); sum += bv[j]; }
        float inv = rcpf(sum);
        sB[t] = make_float4(bv[0] * inv, bv[1] * inv, bv[2] * inv, bv[3] * inv);
        reinterpret_cast<float*>(sB42)[p * 2 + which] = bv[4] * inv;
    }
    __syncthreads();                       // the ONLY block barrier

    // ---- rule activations: 8 pairs, 2 independent accumulation chains ----
    float awA[PAIRS], awB[PAIRS];
    float sp0 = 0.f, sp1 = 0.f;
    #pragma unroll
    for (int m = 0; m < PAIRS; m++) {
        float4 K = sK4[m * 32 + l];
        float a0 = ex2f(fmaf(K.y, Sx, K.x));
        float a1 = ex2f(fmaf(K.w, Sx, K.z));
        awA[m] = a0; awB[m] = a1;
        sp0 += a0; sp1 += a1;
    }
    float spart = sp0 + sp1;
    #pragma unroll
    for (int o = 16; o; o >>= 1) spart += __shfl_xor_sync(0xffffffffu, spart, o);
    const float s = spart;

    // ---- evidential combine: 10 independent product chains (A/B split) ----
    float pA0 = 1.f, pA1 = 1.f, pA2 = 1.f, pA3 = 1.f, pA4 = 1.f;
    float pB0 = 1.f, pB1 = 1.f, pB2 = 1.f, pB3 = 1.f, pB4 = 1.f;
    #pragma unroll
    for (int m = 0; m < PAIRS; m++) {
        int rA = m * 64 + l;
        float ratioA = __fdividef(awA[m], s - awA[m]);
        float ratioB = __fdividef(awB[m], s - awB[m]);
        float4 bA = sB[rA];
        float4 bB = sB[rA + 32];
        float2 b4 = sB42[m * 32 + l];
        pA0 *= fmaf(ratioA, bA.x, 1.0f);
        pA1 *= fmaf(ratioA, bA.y, 1.0f);
        pA2 *= fmaf(ratioA, bA.z, 1.0f);
        pA3 *= fmaf(ratioA, bA.w, 1.0f);
        pA4 *= fmaf(ratioA, b4.x, 1.0f);
        pB0 *= fmaf(ratioB, bB.x, 1.0f);
        pB1 *= fmaf(ratioB, bB.y, 1.0f);
        pB2 *= fmaf(ratioB, bB.z, 1.0f);
        pB3 *= fmaf(ratioB, bB.w, 1.0f);
        pB4 *= fmaf(ratioB, b4.y, 1.0f);
    }
    float p0 = pA0 * pB0, p1 = pA1 * pB1, p2 = pA2 * pB2,
          p3 = pA3 * pB3, p4 = pA4 * pB4;
    // 5 independent cross-lane product reductions (pipelined SHFL chains)
    #pragma unroll
    for (int o = 16; o; o >>= 1) {
        p0 *= __shfl_xor_sync(0xffffffffu, p0, o);
        p1 *= __shfl_xor_sync(0xffffffffu, p1, o);
        p2 *= __shfl_xor_sync(0xffffffffu, p2, o);
        p3 *= __shfl_xor_sync(0xffffffffu, p3, o);
        p4 *= __shfl_xor_sync(0xffffffffu, p4, o);
    }

    if (l == 0) {
        float b0 = p0 - 1.f, b1 = p1 - 1.f, b2 = p2 - 1.f, b3 = p3 - 1.f, b4 = p4 - 1.f;
        float bsum = b0 + b1 + b2 + b3 + b4;
        float acc = fmaf(b0, -0.5f, 0.f);
        acc = fmaf(b2, 0.5f, acc);
        acc = fmaf(b3, 1.0f, acc);
        acc = fmaf(b4, 1.5f, acc);
        out[row] = __fdividef(acc, bsum);
    }
}

extern "C" void kernel_launch(void* const* d_in, const int* in_sizes, int n_in,
                              void* d_out, int out_size) {
    const float* x = (const float*)d_in[0];
    const float* a = (const float*)d_in[1];
    const float* b = (const float*)d_in[2];
    const float* r = (const float*)d_in[3];
    const float* d = (const float*)d_in[4];
    float* out = (float*)d_out;

    fused_kernel<<<BLOCKS, THREADS>>>(x, a, b, r, d, out);
}

// round 17
// speedup vs baseline: 2.5990x; 1.1643x over previous
#include <cuda_runtime.h>
#include <math.h>

#define RULES 512
#define FEAT  128
#define RES   5
#define BATCH 2048
#define WARPS_PER_BLOCK 8
#define THREADS (WARPS_PER_BLOCK * 32)          // 256
#define BLOCKS  (BATCH / WARPS_PER_BLOCK)       // 256 blocks -> all 148 SMs engaged,
                                                // ~2 co-resident blocks/SM overlap stalls
#define PAIRS 8                                 // 16 rules/lane as 8 (A,B) pairs
#define RULES_PER_THREAD 2                      // 256 threads prep 512 rules

#define LOG2E 1.4426950408889634f

__device__ __forceinline__ float ex2f(float v) {
    float r;
    asm("ex2.approx.f32 %0, %1;" : "=f"(r) : "f"(v));
    return r;
}
__device__ __forceinline__ float rcpf(float v) {
    float r;
    asm("rcp.approx.f32 %0, %1;" : "=f"(r) : "f"(v));
    return r;
}

__global__ void __launch_bounds__(THREADS, 2)
fused_kernel(const float* __restrict__ x,
             const float* __restrict__ a,
             const float* __restrict__ bmat,
             const float* __restrict__ r,
             const float* __restrict__ d,
             float* __restrict__ out) {
    // Rule-PAIR packed constants. Pair p = m*32+l covers rules A=m*64+l, B=A+32.
    // sK4[p] = (k0A, k1A, k0B, k1B) log2-domain, 1/5 x-scale folded into k1,
    // row-common quadratic term dropped (cancels in ratio = aw/(s-aw)).
    __shared__ float4 sK4[RULES / 2];
    __shared__ float4 sB[RULES];          // beliefs 0..3 per rule
    __shared__ float2 sB42[RULES / 2];    // (b4 of A, b4 of B) per pair

    const int t = threadIdx.x;
    const int l = t & 31;
    const int w = t >> 5;
    const int row = blockIdx.x * WARPS_PER_BLOCK + w;

    // Issue ALL global loads first; latency overlaps Sx tree + prep math.
    const float4 xv = *reinterpret_cast<const float4*>(x + row * FEAT + l * 4);
    float av[RULES_PER_THREAD], rv[RULES_PER_THREAD], bv[RULES_PER_THREAD][RES];
    #pragma unroll
    for (int q = 0; q < RULES_PER_THREAD; q++) {
        const int rule = t + q * THREADS;
        av[q] = a[rule];
        rv[q] = r[rule];
        #pragma unroll
        for (int j = 0; j < RES; j++) bv[q][j] = bmat[rule * RES + j];
    }
    const float ed = __expf(d[0]);

    // ---- Sx over raw features (scale folded into K1); hides prep LDG latency
    float Sx = (xv.x + xv.y) + (xv.z + xv.w);
    #pragma unroll
    for (int o = 16; o; o >>= 1) Sx += __shfl_xor_sync(0xffffffffu, Sx, o);

    // ---- prep: thread t preps rules t and t+256; pair-packed layout ----
    #pragma unroll
    for (int q = 0; q < RULES_PER_THREAD; q++) {
        const int rule  = t + q * THREADS;
        const int m     = rule >> 6;       // pair group 0..7
        const int which = (rule >> 5) & 1; // A(0) or B(1) within pair
        const int p     = m * 32 + (rule & 31);

        float k1 = 0.4f * ed * av[q];                     // 2*e^d*a * (1/5)
        float k0 = rv[q] - ed * 128.0f * av[q] * av[q];   // common-mode term dropped
        float* kf = reinterpret_cast<float*>(sK4);
        kf[p * 4 + which * 2 + 0] = k0 * LOG2E;
        kf[p * 4 + which * 2 + 1] = k1 * LOG2E;

        float mx = fmaxf(fmaxf(fmaxf(bv[q][0], bv[q][1]), fmaxf(bv[q][2], bv[q][3])), bv[q][4]);
        float sum = 0.f;
        #pragma unroll
        for (int j = 0; j < RES; j++) { bv[q][j] = ex2f((bv[q][j] - mx) * LOG2E); sum += bv[q][j]; }
        float inv = rcpf(sum);
        sB[rule] = make_float4(bv[q][0] * inv, bv[q][1] * inv, bv[q][2] * inv, bv[q][3] * inv);
        reinterpret_cast<float*>(sB42)[p * 2 + which] = bv[q][4] * inv;
    }
    __syncthreads();                       // the ONLY block barrier (8 warps wide)

    // ---- rule activations: 8 pairs, 2 independent accumulation chains ----
    float awA[PAIRS], awB[PAIRS];
    float sp0 = 0.f, sp1 = 0.f;
    #pragma unroll
    for (int m = 0; m < PAIRS; m++) {
        float4 K = sK4[m * 32 + l];
        float a0 = ex2f(fmaf(K.y, Sx, K.x));
        float a1 = ex2f(fmaf(K.w, Sx, K.z));
        awA[m] = a0; awB[m] = a1;
        sp0 += a0; sp1 += a1;
    }
    float spart = sp0 + sp1;
    #pragma unroll
    for (int o = 16; o; o >>= 1) spart += __shfl_xor_sync(0xffffffffu, spart, o);
    const float s = spart;

    // ---- evidential combine: 10 independent product chains (A/B split) ----
    float pA0 = 1.f, pA1 = 1.f, pA2 = 1.f, pA3 = 1.f, pA4 = 1.f;
    float pB0 = 1.f, pB1 = 1.f, pB2 = 1.f, pB3 = 1.f, pB4 = 1.f;
    #pragma unroll
    for (int m = 0; m < PAIRS; m++) {
        int rA = m * 64 + l;
        float ratioA = __fdividef(awA[m], s - awA[m]);
        float ratioB = __fdividef(awB[m], s - awB[m]);
        float4 bA = sB[rA];
        float4 bB = sB[rA + 32];
        float2 b4 = sB42[m * 32 + l];
        pA0 *= fmaf(ratioA, bA.x, 1.0f);
        pA1 *= fmaf(ratioA, bA.y, 1.0f);
        pA2 *= fmaf(ratioA, bA.z, 1.0f);
        pA3 *= fmaf(ratioA, bA.w, 1.0f);
        pA4 *= fmaf(ratioA, b4.x, 1.0f);
        pB0 *= fmaf(ratioB, bB.x, 1.0f);
        pB1 *= fmaf(ratioB, bB.y, 1.0f);
        pB2 *= fmaf(ratioB, bB.z, 1.0f);
        pB3 *= fmaf(ratioB, bB.w, 1.0f);
        pB4 *= fmaf(ratioB, b4.y, 1.0f);
    }
    float p0 = pA0 * pB0, p1 = pA1 * pB1, p2 = pA2 * pB2,
          p3 = pA3 * pB3, p4 = pA4 * pB4;
    // 5 independent cross-lane product reductions (pipelined SHFL chains)
    #pragma unroll
    for (int o = 16; o; o >>= 1) {
        p0 *= __shfl_xor_sync(0xffffffffu, p0, o);
        p1 *= __shfl_xor_sync(0xffffffffu, p1, o);
        p2 *= __shfl_xor_sync(0xffffffffu, p2, o);
        p3 *= __shfl_xor_sync(0xffffffffu, p3, o);
        p4 *= __shfl_xor_sync(0xffffffffu, p4, o);
    }

    if (l == 0) {
        float b0 = p0 - 1.f, b1 = p1 - 1.f, b2 = p2 - 1.f, b3 = p3 - 1.f, b4 = p4 - 1.f;
        float bsum = b0 + b1 + b2 + b3 + b4;
        float acc = fmaf(b0, -0.5f, 0.f);
        acc = fmaf(b2, 0.5f, acc);
        acc = fmaf(b3, 1.0f, acc);
        acc = fmaf(b4, 1.5f, acc);
        out[row] = __fdividef(acc, bsum);
    }
}

extern "C" void kernel_launch(void* const* d_in, const int* in_sizes, int n_in,
                              void* d_out, int out_size) {
    const float* x = (const float*)d_in[0];
    const float* a = (const float*)d_in[1];
    const float* b = (const float*)d_in[2];
    const float* r = (const float*)d_in[3];
    const float* d = (const float*)d_in[4];
    float* out = (float*)d_out;

    fused_kernel<<<BLOCKS, THREADS>>>(x, a, b, r, d, out);
}